// round 1
// baseline (speedup 1.0000x reference)
#include <cuda_runtime.h>
#include <cstdint>

// Problem constants (fixed by the reference)
constexpr int N_NODES = 100000;
constexpr int N_EDGES = 640000;
constexpr int D       = 128;

// ---------------------------------------------------------------------------
// Scratch (allocation-free: __device__ globals)
// ---------------------------------------------------------------------------
__device__ float g_deg_out[N_NODES];
__device__ float g_deg_in [N_NODES];
__device__ float g_inv_out[N_NODES];
__device__ float g_inv_in [N_NODES];
__device__ float g_agg[(size_t)N_NODES * D];   // scatter accumulator
__device__ float g_h1 [(size_t)N_NODES * D];   // layer-1 activations

// ---------------------------------------------------------------------------
// Zeroing kernels (reference device symbols directly; no symbol-addr API)
// ---------------------------------------------------------------------------
__global__ void zero_deg_kernel() {
    int i = blockIdx.x * blockDim.x + threadIdx.x;
    if (i < N_NODES) { g_deg_out[i] = 0.0f; g_deg_in[i] = 0.0f; }
}

__global__ void zero_agg_kernel() {
    size_t i = (size_t)blockIdx.x * blockDim.x + threadIdx.x;
    size_t n4 = (size_t)N_NODES * D / 4;
    if (i < n4) reinterpret_cast<float4*>(g_agg)[i] = make_float4(0.f, 0.f, 0.f, 0.f);
}

// ---------------------------------------------------------------------------
// Degree computation: one thread per edge, fire-and-forget float reductions
// ---------------------------------------------------------------------------
__global__ void degree_kernel(const int* __restrict__ src,
                              const int* __restrict__ dst) {
    int i = blockIdx.x * blockDim.x + threadIdx.x;
    if (i < N_EDGES) {
        atomicAdd(&g_deg_out[src[i]], 1.0f);
        atomicAdd(&g_deg_in [dst[i]], 1.0f);
    }
}

__global__ void invsqrt_kernel() {
    int i = blockIdx.x * blockDim.x + threadIdx.x;
    if (i < N_NODES) {
        g_inv_out[i] = 1.0f / sqrtf(fmaxf(g_deg_out[i], 1.0f));
        g_inv_in [i] = 1.0f / sqrtf(fmaxf(g_deg_in [i], 1.0f));
    }
}

// ---------------------------------------------------------------------------
// Edge scatter: agg[dst] += x[src] * inv_sqrt_out[src]
// One warp handles 32 edges. Lane-coalesced index loads, shfl broadcast.
// Each lane owns 4 contiguous features: 1 float4 gather + 1 red.v4 per edge.
// ---------------------------------------------------------------------------
__global__ void __launch_bounds__(256)
scatter_kernel(const float* __restrict__ x,
               const int*   __restrict__ src,
               const int*   __restrict__ dst) {
    int gw   = (blockIdx.x * blockDim.x + threadIdx.x) >> 5;
    int lane = threadIdx.x & 31;
    int e0   = gw * 32;
    if (e0 >= N_EDGES) return;

    int e = e0 + lane;
    int s = 0, d = 0;
    float sc = 0.0f;
    if (e < N_EDGES) {
        s  = src[e];
        d  = dst[e];
        sc = g_inv_out[s];
    }
    int cnt = min(32, N_EDGES - e0);
    const int c4 = lane * 4;

    for (int i = 0; i < cnt; i++) {
        int   ss = __shfl_sync(0xffffffffu, s,  i);
        int   dd = __shfl_sync(0xffffffffu, d,  i);
        float c  = __shfl_sync(0xffffffffu, sc, i);

        float4 v = *reinterpret_cast<const float4*>(x + (size_t)ss * D + c4);
        v.x *= c; v.y *= c; v.z *= c; v.w *= c;

        float* p = g_agg + (size_t)dd * D + c4;
        asm volatile("red.global.add.v4.f32 [%0], {%1, %2, %3, %4};"
                     :: "l"(p), "f"(v.x), "f"(v.y), "f"(v.z), "f"(v.w)
                     : "memory");
    }
}

// ---------------------------------------------------------------------------
// Fused GEMM epilogue: out = relu?((agg * inv_sqrt_in[row]) @ W + b)
// 128x128 tile, BK=8, 8x8 register micro-tiles, 256 threads.
// ---------------------------------------------------------------------------
__global__ void __launch_bounds__(256)
gemm_bias_kernel(const float* __restrict__ A,
                 const float* __restrict__ W,
                 const float* __restrict__ bias,
                 float*       __restrict__ out,
                 int relu) {
    __shared__ float As[8][128];   // transposed A tile: As[k][row]
    __shared__ float Bs[8][128];   // W slice: Bs[k][col]

    const int t    = threadIdx.x;
    const int row0 = blockIdx.x * 128;

    // A-load mapping: 2 threads per row, each loads 4 k-values
    const int arow = t >> 1;
    const int ak4  = (t & 1) * 4;
    // B-load mapping: 32 threads per k-row, each loads 4 cols
    const int bkk  = t >> 5;
    const int bc4  = (t & 31) * 4;
    // compute mapping: 16x16 grid of threads, 8x8 micro-tile each
    const int ty   = t >> 4;
    const int tx   = t & 15;
    const int rowf = ty * 8;
    const int colf = tx * 8;

    const int  gr_a  = row0 + arow;
    const bool aval  = gr_a < N_NODES;
    const float scale = aval ? g_inv_in[gr_a] : 0.0f;
    const float* aptr = A + (size_t)(aval ? gr_a : 0) * D + ak4;

    float acc[8][8];
    #pragma unroll
    for (int i = 0; i < 8; i++)
        #pragma unroll
        for (int j = 0; j < 8; j++) acc[i][j] = 0.0f;

    for (int kc = 0; kc < D; kc += 8) {
        float4 av = make_float4(0.f, 0.f, 0.f, 0.f);
        if (aval) av = *reinterpret_cast<const float4*>(aptr + kc);
        As[ak4 + 0][arow] = av.x * scale;
        As[ak4 + 1][arow] = av.y * scale;
        As[ak4 + 2][arow] = av.z * scale;
        As[ak4 + 3][arow] = av.w * scale;

        float4 bv = *reinterpret_cast<const float4*>(W + (size_t)(kc + bkk) * D + bc4);
        *reinterpret_cast<float4*>(&Bs[bkk][bc4]) = bv;

        __syncthreads();

        #pragma unroll
        for (int kk = 0; kk < 8; kk++) {
            float4 a0 = *reinterpret_cast<const float4*>(&As[kk][rowf]);
            float4 a1 = *reinterpret_cast<const float4*>(&As[kk][rowf + 4]);
            float4 b0 = *reinterpret_cast<const float4*>(&Bs[kk][colf]);
            float4 b1 = *reinterpret_cast<const float4*>(&Bs[kk][colf + 4]);
            float a[8] = {a0.x, a0.y, a0.z, a0.w, a1.x, a1.y, a1.z, a1.w};
            float b[8] = {b0.x, b0.y, b0.z, b0.w, b1.x, b1.y, b1.z, b1.w};
            #pragma unroll
            for (int i = 0; i < 8; i++)
                #pragma unroll
                for (int j = 0; j < 8; j++)
                    acc[i][j] += a[i] * b[j];
        }
        __syncthreads();
    }

    // Epilogue: bias (+ relu), float4 stores
    float4 bi0 = *reinterpret_cast<const float4*>(bias + colf);
    float4 bi1 = *reinterpret_cast<const float4*>(bias + colf + 4);
    float bb[8] = {bi0.x, bi0.y, bi0.z, bi0.w, bi1.x, bi1.y, bi1.z, bi1.w};

    #pragma unroll
    for (int i = 0; i < 8; i++) {
        int gr = row0 + rowf + i;
        if (gr < N_NODES) {
            float v[8];
            #pragma unroll
            for (int j = 0; j < 8; j++) {
                v[j] = acc[i][j] + bb[j];
                if (relu) v[j] = fmaxf(v[j], 0.0f);
            }
            float4 o0 = make_float4(v[0], v[1], v[2], v[3]);
            float4 o1 = make_float4(v[4], v[5], v[6], v[7]);
            *reinterpret_cast<float4*>(out + (size_t)gr * D + colf)     = o0;
            *reinterpret_cast<float4*>(out + (size_t)gr * D + colf + 4) = o1;
        }
    }
}

// ---------------------------------------------------------------------------
// Launch sequence (graph-capturable: kernel launches only, default stream)
// Inputs (metadata order): t, h, src, dst, W1, b1, W2, b2
// ---------------------------------------------------------------------------
extern "C" void kernel_launch(void* const* d_in, const int* in_sizes, int n_in,
                              void* d_out, int out_size) {
    const float* h   = (const float*)d_in[1];
    const int*   src = (const int*)  d_in[2];
    const int*   dst = (const int*)  d_in[3];
    const float* W1  = (const float*)d_in[4];
    const float* b1  = (const float*)d_in[5];
    const float* W2  = (const float*)d_in[6];
    const float* b2  = (const float*)d_in[7];
    float* out = (float*)d_out;

    // device-symbol pointers for kernel args (symbols used directly in-kernel;
    // we only need raw pointers for agg / h1 as GEMM/scatter inputs)
    // g_agg / g_h1 are accessed via their device-symbol identity inside the
    // kernels that hard-reference them; for kernels taking pointers we pass
    // them through small launcher kernels? No — simplest: kernels that need
    // them as *inputs* take pointers; we obtain those pointers via the fact
    // that device symbols can be referenced from device code only. So the
    // pointer-taking kernels below receive nullptr markers and switch.
    // --> Instead we just declare thin wrappers: scatter reads x (pointer),
    //     writes g_agg (symbol). gemm reads A (pointer) — we must pass g_agg's
    //     address. Use cudaGetSymbolAddress (host API, not an allocation, and
    //     not a stream operation — safe under graph capture).
    static float* p_agg = nullptr;
    static float* p_h1  = nullptr;
    if (!p_agg) {
        void* pa = nullptr; void* ph = nullptr;
        cudaGetSymbolAddress(&pa, g_agg);
        cudaGetSymbolAddress(&ph, g_h1);
        p_agg = (float*)pa;
        p_h1  = (float*)ph;
    }

    const int TB = 256;
    const int blocks_nodes = (N_NODES + TB - 1) / TB;                 // 391
    const int blocks_edges = (N_EDGES + TB - 1) / TB;                 // 2500
    const int blocks_scat  = ((N_EDGES + 31) / 32 * 32 + TB - 1) / TB;// 2500
    const int blocks_zero  = (int)(((size_t)N_NODES * D / 4 + TB - 1) / TB);
    const int blocks_gemm  = (N_NODES + 127) / 128;                   // 782

    // degrees + normalization
    zero_deg_kernel<<<blocks_nodes, TB>>>();
    degree_kernel<<<blocks_edges, TB>>>(src, dst);
    invsqrt_kernel<<<blocks_nodes, TB>>>();

    // layer 1
    zero_agg_kernel<<<blocks_zero, TB>>>();
    scatter_kernel<<<blocks_scat, TB>>>(h, src, dst);
    gemm_bias_kernel<<<blocks_gemm, TB>>>(p_agg, W1, b1, p_h1, /*relu=*/1);

    // layer 2
    zero_agg_kernel<<<blocks_zero, TB>>>();
    scatter_kernel<<<blocks_scat, TB>>>(p_h1, src, dst);
    gemm_bias_kernel<<<blocks_gemm, TB>>>(p_agg, W2, b2, out, /*relu=*/0);
}

// round 3
// speedup vs baseline: 1.4527x; 1.4527x over previous
#include <cuda_runtime.h>
#include <cuda_bf16.h>
#include <cstdint>

// Problem constants (fixed by the reference)
constexpr int N_NODES = 100000;
constexpr int N_EDGES = 640000;
constexpr int D       = 128;

// ---------------------------------------------------------------------------
// Scratch (allocation-free: __device__ globals)
// ---------------------------------------------------------------------------
__device__ float g_deg_out[N_NODES];
__device__ float g_deg_in [N_NODES];
__device__ float g_inv_out[N_NODES];
__device__ float g_inv_in [N_NODES];
__device__ float g_agg[(size_t)N_NODES * D];     // scatter accumulator
__device__ float g_h1 [(size_t)N_NODES * D];     // layer-1 activations
// W split to bf16 hi/lo, stored TRANSPOSED: [n][k]
__device__ __nv_bfloat16 g_whiT[2][D * D];
__device__ __nv_bfloat16 g_wloT[2][D * D];

// ---------------------------------------------------------------------------
// Zeroing
// ---------------------------------------------------------------------------
__global__ void zero_deg_kernel() {
    int i = blockIdx.x * blockDim.x + threadIdx.x;
    if (i < N_NODES) { g_deg_out[i] = 0.0f; g_deg_in[i] = 0.0f; }
}

__global__ void zero_agg_kernel() {
    size_t i = (size_t)blockIdx.x * blockDim.x + threadIdx.x;
    size_t n4 = (size_t)N_NODES * D / 4;
    if (i < n4) reinterpret_cast<float4*>(g_agg)[i] = make_float4(0.f, 0.f, 0.f, 0.f);
}

// ---------------------------------------------------------------------------
// Degrees + inv-sqrt
// ---------------------------------------------------------------------------
__global__ void degree_kernel(const int* __restrict__ src,
                              const int* __restrict__ dst) {
    int i = blockIdx.x * blockDim.x + threadIdx.x;
    if (i < N_EDGES) {
        atomicAdd(&g_deg_out[src[i]], 1.0f);
        atomicAdd(&g_deg_in [dst[i]], 1.0f);
    }
}

__global__ void invsqrt_kernel() {
    int i = blockIdx.x * blockDim.x + threadIdx.x;
    if (i < N_NODES) {
        g_inv_out[i] = 1.0f / sqrtf(fmaxf(g_deg_out[i], 1.0f));
        g_inv_in [i] = 1.0f / sqrtf(fmaxf(g_deg_in [i], 1.0f));
    }
}

// ---------------------------------------------------------------------------
// W pre-split: whiT[n][k] = bf16(W[k][n]); wloT = bf16(residual)
// ---------------------------------------------------------------------------
__global__ void convert_w_kernel(const float* __restrict__ W, int layer) {
    int i = blockIdx.x * blockDim.x + threadIdx.x;
    if (i < D * D) {
        int n = i / D, k = i % D;
        float w = W[k * D + n];
        __nv_bfloat16 hi = __float2bfloat16(w);
        float lo = w - __bfloat162float(hi);
        g_whiT[layer][i] = hi;
        g_wloT[layer][i] = __float2bfloat16(lo);
    }
}

// ---------------------------------------------------------------------------
// Edge scatter: agg[dst] += x[src] * inv_sqrt_out[src]   (red.global.add.v4)
// ---------------------------------------------------------------------------
__global__ void __launch_bounds__(256)
scatter_kernel(const float* __restrict__ x,
               const int*   __restrict__ src,
               const int*   __restrict__ dst) {
    int gw   = (blockIdx.x * blockDim.x + threadIdx.x) >> 5;
    int lane = threadIdx.x & 31;
    int e0   = gw * 32;
    if (e0 >= N_EDGES) return;

    int e = e0 + lane;
    int s = 0, d = 0;
    float sc = 0.0f;
    if (e < N_EDGES) {
        s  = src[e];
        d  = dst[e];
        sc = g_inv_out[s];
    }
    int cnt = min(32, N_EDGES - e0);
    const int c4 = lane * 4;

    for (int i = 0; i < cnt; i++) {
        int   ss = __shfl_sync(0xffffffffu, s,  i);
        int   dd = __shfl_sync(0xffffffffu, d,  i);
        float c  = __shfl_sync(0xffffffffu, sc, i);

        float4 v = *reinterpret_cast<const float4*>(x + (size_t)ss * D + c4);
        v.x *= c; v.y *= c; v.z *= c; v.w *= c;

        float* p = g_agg + (size_t)dd * D + c4;
        asm volatile("red.global.add.v4.f32 [%0], {%1, %2, %3, %4};"
                     :: "l"(p), "f"(v.x), "f"(v.y), "f"(v.z), "f"(v.w)
                     : "memory");
    }
}

// ---------------------------------------------------------------------------
// Tensor-core GEMM: out = relu?( inv_sqrt_in[row] * (A @ W) + b )
// A fp32 split on-the-fly to bf16 hi/lo; W pre-split (transposed, bf16).
// 3-product fp32 emulation: Ahi*Whi + Ahi*Wlo + Alo*Whi.
// CTA: 128 rows x 128 cols, 256 thr (8 warps, 4x2), warp = 32x64.
// ---------------------------------------------------------------------------
__device__ __forceinline__ void mma_bf16(float* c, const uint32_t* a, const uint32_t* b) {
    asm volatile(
        "mma.sync.aligned.m16n8k16.row.col.f32.bf16.bf16.f32 "
        "{%0,%1,%2,%3}, {%4,%5,%6,%7}, {%8,%9}, {%0,%1,%2,%3};\n"
        : "+f"(c[0]), "+f"(c[1]), "+f"(c[2]), "+f"(c[3])
        : "r"(a[0]), "r"(a[1]), "r"(a[2]), "r"(a[3]), "r"(b[0]), "r"(b[1]));
}

constexpr int LDSB = 40;  // padded smem stride (bf16 units): conflict-free frag loads

__global__ void __launch_bounds__(256, 2)
gemm_tc_kernel(const float* __restrict__ A, int layer,
               const float* __restrict__ bias,
               float*       __restrict__ out, int relu) {
    __shared__ __align__(16) __nv_bfloat16 Ashi[128 * LDSB];
    __shared__ __align__(16) __nv_bfloat16 Aslo[128 * LDSB];
    __shared__ __align__(16) __nv_bfloat16 Bshi[128 * LDSB];
    __shared__ __align__(16) __nv_bfloat16 Bslo[128 * LDSB];

    const int t    = threadIdx.x;
    const int lane = t & 31;
    const int w    = t >> 5;
    const int wr   = w >> 1;          // 0..3 -> rows wr*32
    const int wc   = w & 1;           // 0..1 -> cols wc*64
    const int row0 = blockIdx.x * 128;

    const __nv_bfloat16* WhiT = g_whiT[layer];
    const __nv_bfloat16* WloT = g_wloT[layer];

    float acc[2][8][4];
    #pragma unroll
    for (int mt = 0; mt < 2; mt++)
        #pragma unroll
        for (int nt = 0; nt < 8; nt++)
            #pragma unroll
            for (int r = 0; r < 4; r++) acc[mt][nt][r] = 0.0f;

    const int l4 = lane >> 2;         // 0..7
    const int l2 = (lane & 3) * 2;    // 0,2,4,6

    for (int kc = 0; kc < D; kc += 32) {
        // ---- stage A chunk (128 x 32 fp32), split to bf16 hi/lo ----
        #pragma unroll
        for (int j = 0; j < 4; j++) {
            int idx = t + 256 * j;         // float4 index 0..1023
            int r   = idx >> 3;            // row in tile
            int c4  = (idx & 7) * 4;       // k offset
            int gr  = row0 + r;
            float4 v = make_float4(0.f, 0.f, 0.f, 0.f);
            if (gr < N_NODES)
                v = *reinterpret_cast<const float4*>(A + (size_t)gr * D + kc + c4);
            __nv_bfloat16 hx = __float2bfloat16(v.x);
            __nv_bfloat16 hy = __float2bfloat16(v.y);
            __nv_bfloat16 hz = __float2bfloat16(v.z);
            __nv_bfloat16 hw = __float2bfloat16(v.w);
            __nv_bfloat162 h01; h01.x = hx; h01.y = hy;
            __nv_bfloat162 h23; h23.x = hz; h23.y = hw;
            __nv_bfloat162 l01, l23;
            l01.x = __float2bfloat16(v.x - __bfloat162float(hx));
            l01.y = __float2bfloat16(v.y - __bfloat162float(hy));
            l23.x = __float2bfloat16(v.z - __bfloat162float(hz));
            l23.y = __float2bfloat16(v.w - __bfloat162float(hw));
            *reinterpret_cast<__nv_bfloat162*>(&Ashi[r * LDSB + c4])     = h01;
            *reinterpret_cast<__nv_bfloat162*>(&Ashi[r * LDSB + c4 + 2]) = h23;
            *reinterpret_cast<__nv_bfloat162*>(&Aslo[r * LDSB + c4])     = l01;
            *reinterpret_cast<__nv_bfloat162*>(&Aslo[r * LDSB + c4 + 2]) = l23;
        }
        // ---- stage B chunk: WT[n][kc..kc+31] bf16 hi/lo ----
        // 128 rows x 32 bf16 = 512 uint4 chunks (hi and lo each): 4 chunks/row.
        #pragma unroll
        for (int j = 0; j < 2; j++) {
            int idx = t + 256 * j;        // 0..511
            int n   = idx >> 2;           // 0..127
            int k8  = (idx & 3) * 8;      // 0,8,16,24
            uint4 vh = *reinterpret_cast<const uint4*>(WhiT + n * D + kc + k8);
            uint4 vl = *reinterpret_cast<const uint4*>(WloT + n * D + kc + k8);
            *reinterpret_cast<uint4*>(&Bshi[n * LDSB + k8]) = vh;
            *reinterpret_cast<uint4*>(&Bslo[n * LDSB + k8]) = vl;
        }
        __syncthreads();

        // ---- compute: 2 k16 steps ----
        #pragma unroll
        for (int kk = 0; kk < 32; kk += 16) {
            // A fragments (canonical m16n8k16 row-major map)
            uint32_t afh[2][4], afl[2][4];
            #pragma unroll
            for (int mt = 0; mt < 2; mt++) {
                int ar = wr * 32 + mt * 16;
                int k0 = kk + l2;
                afh[mt][0] = *reinterpret_cast<const uint32_t*>(&Ashi[(ar + l4)     * LDSB + k0]);
                afh[mt][1] = *reinterpret_cast<const uint32_t*>(&Ashi[(ar + l4 + 8) * LDSB + k0]);
                afh[mt][2] = *reinterpret_cast<const uint32_t*>(&Ashi[(ar + l4)     * LDSB + k0 + 8]);
                afh[mt][3] = *reinterpret_cast<const uint32_t*>(&Ashi[(ar + l4 + 8) * LDSB + k0 + 8]);
                afl[mt][0] = *reinterpret_cast<const uint32_t*>(&Aslo[(ar + l4)     * LDSB + k0]);
                afl[mt][1] = *reinterpret_cast<const uint32_t*>(&Aslo[(ar + l4 + 8) * LDSB + k0]);
                afl[mt][2] = *reinterpret_cast<const uint32_t*>(&Aslo[(ar + l4)     * LDSB + k0 + 8]);
                afl[mt][3] = *reinterpret_cast<const uint32_t*>(&Aslo[(ar + l4 + 8) * LDSB + k0 + 8]);
            }
            #pragma unroll
            for (int nt = 0; nt < 8; nt++) {
                int bn = wc * 64 + nt * 8 + l4;
                int k0 = kk + l2;
                uint32_t bfh[2], bfl[2];
                bfh[0] = *reinterpret_cast<const uint32_t*>(&Bshi[bn * LDSB + k0]);
                bfh[1] = *reinterpret_cast<const uint32_t*>(&Bshi[bn * LDSB + k0 + 8]);
                bfl[0] = *reinterpret_cast<const uint32_t*>(&Bslo[bn * LDSB + k0]);
                bfl[1] = *reinterpret_cast<const uint32_t*>(&Bslo[bn * LDSB + k0 + 8]);
                #pragma unroll
                for (int mt = 0; mt < 2; mt++) {
                    mma_bf16(acc[mt][nt], afh[mt], bfh);   // hi*hi
                    mma_bf16(acc[mt][nt], afh[mt], bfl);   // hi*lo
                    mma_bf16(acc[mt][nt], afl[mt], bfh);   // lo*hi
                }
            }
        }
        __syncthreads();
    }

    // ---- epilogue: scale by inv_sqrt_in[row], + bias, relu, store ----
    #pragma unroll
    for (int mt = 0; mt < 2; mt++) {
        int gr0 = row0 + wr * 32 + mt * 16 + l4;
        int gr1 = gr0 + 8;
        float s0 = (gr0 < N_NODES) ? g_inv_in[gr0] : 0.0f;
        float s1 = (gr1 < N_NODES) ? g_inv_in[gr1] : 0.0f;
        #pragma unroll
        for (int nt = 0; nt < 8; nt++) {
            int col = wc * 64 + nt * 8 + l2;
            float2 bb = *reinterpret_cast<const float2*>(bias + col);
            float o0 = acc[mt][nt][0] * s0 + bb.x;
            float o1 = acc[mt][nt][1] * s0 + bb.y;
            float o2 = acc[mt][nt][2] * s1 + bb.x;
            float o3 = acc[mt][nt][3] * s1 + bb.y;
            if (relu) {
                o0 = fmaxf(o0, 0.f); o1 = fmaxf(o1, 0.f);
                o2 = fmaxf(o2, 0.f); o3 = fmaxf(o3, 0.f);
            }
            if (gr0 < N_NODES)
                *reinterpret_cast<float2*>(out + (size_t)gr0 * D + col) = make_float2(o0, o1);
            if (gr1 < N_NODES)
                *reinterpret_cast<float2*>(out + (size_t)gr1 * D + col) = make_float2(o2, o3);
        }
    }
}

// ---------------------------------------------------------------------------
// Launch sequence (graph-capturable)
// Inputs (metadata order): t, h, src, dst, W1, b1, W2, b2
// ---------------------------------------------------------------------------
extern "C" void kernel_launch(void* const* d_in, const int* in_sizes, int n_in,
                              void* d_out, int out_size) {
    const float* h   = (const float*)d_in[1];
    const int*   src = (const int*)  d_in[2];
    const int*   dst = (const int*)  d_in[3];
    const float* W1  = (const float*)d_in[4];
    const float* b1  = (const float*)d_in[5];
    const float* W2  = (const float*)d_in[6];
    const float* b2  = (const float*)d_in[7];
    float* out = (float*)d_out;

    static float* p_agg = nullptr;
    static float* p_h1  = nullptr;
    if (!p_agg) {
        void* pa = nullptr; void* ph = nullptr;
        cudaGetSymbolAddress(&pa, g_agg);
        cudaGetSymbolAddress(&ph, g_h1);
        p_agg = (float*)pa;
        p_h1  = (float*)ph;
    }

    const int TB = 256;
    const int blocks_nodes = (N_NODES + TB - 1) / TB;
    const int blocks_edges = (N_EDGES + TB - 1) / TB;
    const int blocks_zero  = (int)(((size_t)N_NODES * D / 4 + TB - 1) / TB);
    const int blocks_gemm  = (N_NODES + 127) / 128;    // 782
    const int blocks_w     = (D * D + TB - 1) / TB;    // 64

    // degrees + normalization + W pre-split
    zero_deg_kernel<<<blocks_nodes, TB>>>();
    degree_kernel<<<blocks_edges, TB>>>(src, dst);
    invsqrt_kernel<<<blocks_nodes, TB>>>();
    convert_w_kernel<<<blocks_w, TB>>>(W1, 0);
    convert_w_kernel<<<blocks_w, TB>>>(W2, 1);

    // layer 1
    zero_agg_kernel<<<blocks_zero, TB>>>();
    scatter_kernel<<<blocks_edges, TB>>>(h, src, dst);
    gemm_tc_kernel<<<blocks_gemm, TB>>>(p_agg, 0, b1, p_h1, /*relu=*/1);

    // layer 2
    zero_agg_kernel<<<blocks_zero, TB>>>();
    scatter_kernel<<<blocks_edges, TB>>>(p_h1, src, dst);
    gemm_tc_kernel<<<blocks_gemm, TB>>>(p_agg, 1, b2, out, /*relu=*/0);
}

// round 4
// speedup vs baseline: 1.4626x; 1.0068x over previous
#include <cuda_runtime.h>
#include <cuda_bf16.h>
#include <cstdint>

// Problem constants (fixed by the reference)
constexpr int N_NODES = 100000;
constexpr int N_EDGES = 640000;
constexpr int D       = 128;

// ---------------------------------------------------------------------------
// Scratch (allocation-free: __device__ globals)
// ---------------------------------------------------------------------------
__device__ float g_deg_out[N_NODES];
__device__ float g_deg_in [N_NODES];
__device__ float g_inv_out[N_NODES];
__device__ float g_inv_in [N_NODES];
__device__ float g_agg[(size_t)N_NODES * D];     // scatter accumulator
__device__ float g_h1 [(size_t)N_NODES * D];     // layer-1 activations
// W split to bf16 hi/lo, stored TRANSPOSED: [n][k]
__device__ __nv_bfloat16 g_whiT[2][D * D];
__device__ __nv_bfloat16 g_wloT[2][D * D];

// ---------------------------------------------------------------------------
// Init: zero g_agg (float4-wide) and both degree arrays in one kernel
// ---------------------------------------------------------------------------
__global__ void init_kernel() {
    int i = blockIdx.x * blockDim.x + threadIdx.x;
    size_t n4 = (size_t)N_NODES * D / 4;
    if ((size_t)i < n4)
        reinterpret_cast<float4*>(g_agg)[i] = make_float4(0.f, 0.f, 0.f, 0.f);
    if (i < N_NODES) { g_deg_out[i] = 0.0f; g_deg_in[i] = 0.0f; }
}

// ---------------------------------------------------------------------------
// Degrees + inv-sqrt
// ---------------------------------------------------------------------------
__global__ void degree_kernel(const int* __restrict__ src,
                              const int* __restrict__ dst) {
    int i = blockIdx.x * blockDim.x + threadIdx.x;
    if (i < N_EDGES) {
        atomicAdd(&g_deg_out[src[i]], 1.0f);
        atomicAdd(&g_deg_in [dst[i]], 1.0f);
    }
}

__global__ void invsqrt_kernel() {
    int i = blockIdx.x * blockDim.x + threadIdx.x;
    if (i < N_NODES) {
        g_inv_out[i] = 1.0f / sqrtf(fmaxf(g_deg_out[i], 1.0f));
        g_inv_in [i] = 1.0f / sqrtf(fmaxf(g_deg_in [i], 1.0f));
    }
}

// ---------------------------------------------------------------------------
// W pre-split, both layers in one launch, COALESCED reads:
// thread idx -> (layer, k, n) with n fastest => consecutive threads read
// consecutive W elements; transposed write side is fire-and-forget.
// ---------------------------------------------------------------------------
__global__ void convert_w_kernel(const float* __restrict__ W1,
                                 const float* __restrict__ W2) {
    int idx = blockIdx.x * blockDim.x + threadIdx.x;
    if (idx < 2 * D * D) {
        int layer = idx >> 14;            // / (D*D)
        int r     = idx & (D * D - 1);
        int k = r >> 7;                   // / D
        int n = r & (D - 1);
        const float* W = layer ? W2 : W1;
        float w = W[k * D + n];           // coalesced
        __nv_bfloat16 hi = __float2bfloat16(w);
        float lo = w - __bfloat162float(hi);
        g_whiT[layer][n * D + k] = hi;    // transposed store
        g_wloT[layer][n * D + k] = __float2bfloat16(lo);
    }
}

// ---------------------------------------------------------------------------
// Edge scatter: agg[dst] += x[src] * inv_sqrt_out[src]   (red.global.add.v4)
// One warp per 32 edges; whole warp cooperates on one edge's 512B row.
// ---------------------------------------------------------------------------
__global__ void __launch_bounds__(256)
scatter_kernel(const float* __restrict__ x,
               const int*   __restrict__ src,
               const int*   __restrict__ dst) {
    int gw   = (blockIdx.x * blockDim.x + threadIdx.x) >> 5;
    int lane = threadIdx.x & 31;
    int e0   = gw * 32;
    if (e0 >= N_EDGES) return;

    int e = e0 + lane;
    int s = 0, d = 0;
    float sc = 0.0f;
    if (e < N_EDGES) {
        s  = src[e];
        d  = dst[e];
        sc = g_inv_out[s];
    }
    int cnt = min(32, N_EDGES - e0);
    const int c4 = lane * 4;

    for (int i = 0; i < cnt; i++) {
        int   ss = __shfl_sync(0xffffffffu, s,  i);
        int   dd = __shfl_sync(0xffffffffu, d,  i);
        float c  = __shfl_sync(0xffffffffu, sc, i);

        float4 v = *reinterpret_cast<const float4*>(x + (size_t)ss * D + c4);
        v.x *= c; v.y *= c; v.z *= c; v.w *= c;

        float* p = g_agg + (size_t)dd * D + c4;
        asm volatile("red.global.add.v4.f32 [%0], {%1, %2, %3, %4};"
                     :: "l"(p), "f"(v.x), "f"(v.y), "f"(v.z), "f"(v.w)
                     : "memory");
    }
}

// ---------------------------------------------------------------------------
// Tensor-core GEMM: out = relu?( inv_sqrt_in[row] * (A @ W) + b )
// A fp32 split on-the-fly to bf16 hi/lo; W pre-split (transposed, bf16).
// 3-product fp32 emulation: Ahi*Whi + Ahi*Wlo + Alo*Whi.
// CTA: 128 rows x 128 cols, 256 thr (8 warps, 4x2), warp = 32x64.
// zero_a: CTA zeroes its exclusively-owned A rows after consuming them,
//         preparing g_agg for the next layer's scatter (replaces zero_agg).
// ---------------------------------------------------------------------------
__device__ __forceinline__ void mma_bf16(float* c, const uint32_t* a, const uint32_t* b) {
    asm volatile(
        "mma.sync.aligned.m16n8k16.row.col.f32.bf16.bf16.f32 "
        "{%0,%1,%2,%3}, {%4,%5,%6,%7}, {%8,%9}, {%0,%1,%2,%3};\n"
        : "+f"(c[0]), "+f"(c[1]), "+f"(c[2]), "+f"(c[3])
        : "r"(a[0]), "r"(a[1]), "r"(a[2]), "r"(a[3]), "r"(b[0]), "r"(b[1]));
}

constexpr int LDSB = 40;  // padded smem stride (bf16 units): conflict-free frag loads

__global__ void __launch_bounds__(256, 2)
gemm_tc_kernel(float* __restrict__ A, int layer,
               const float* __restrict__ bias,
               float*       __restrict__ out, int relu, int zero_a) {
    __shared__ __align__(16) __nv_bfloat16 Ashi[128 * LDSB];
    __shared__ __align__(16) __nv_bfloat16 Aslo[128 * LDSB];
    __shared__ __align__(16) __nv_bfloat16 Bshi[128 * LDSB];
    __shared__ __align__(16) __nv_bfloat16 Bslo[128 * LDSB];

    const int t    = threadIdx.x;
    const int lane = t & 31;
    const int w    = t >> 5;
    const int wr   = w >> 1;          // 0..3 -> rows wr*32
    const int wc   = w & 1;           // 0..1 -> cols wc*64
    const int row0 = blockIdx.x * 128;

    const __nv_bfloat16* WhiT = g_whiT[layer];
    const __nv_bfloat16* WloT = g_wloT[layer];

    float acc[2][8][4];
    #pragma unroll
    for (int mt = 0; mt < 2; mt++)
        #pragma unroll
        for (int nt = 0; nt < 8; nt++)
            #pragma unroll
            for (int r = 0; r < 4; r++) acc[mt][nt][r] = 0.0f;

    const int l4 = lane >> 2;         // 0..7
    const int l2 = (lane & 3) * 2;    // 0,2,4,6

    for (int kc = 0; kc < D; kc += 32) {
        // ---- stage A chunk (128 x 32 fp32), split to bf16 hi/lo ----
        #pragma unroll
        for (int j = 0; j < 4; j++) {
            int idx = t + 256 * j;         // float4 index 0..1023
            int r   = idx >> 3;            // row in tile
            int c4  = (idx & 7) * 4;       // k offset
            int gr  = row0 + r;
            float4 v = make_float4(0.f, 0.f, 0.f, 0.f);
            if (gr < N_NODES)
                v = *reinterpret_cast<const float4*>(A + (size_t)gr * D + kc + c4);
            __nv_bfloat16 hx = __float2bfloat16(v.x);
            __nv_bfloat16 hy = __float2bfloat16(v.y);
            __nv_bfloat16 hz = __float2bfloat16(v.z);
            __nv_bfloat16 hw = __float2bfloat16(v.w);
            __nv_bfloat162 h01; h01.x = hx; h01.y = hy;
            __nv_bfloat162 h23; h23.x = hz; h23.y = hw;
            __nv_bfloat162 l01, l23;
            l01.x = __float2bfloat16(v.x - __bfloat162float(hx));
            l01.y = __float2bfloat16(v.y - __bfloat162float(hy));
            l23.x = __float2bfloat16(v.z - __bfloat162float(hz));
            l23.y = __float2bfloat16(v.w - __bfloat162float(hw));
            *reinterpret_cast<__nv_bfloat162*>(&Ashi[r * LDSB + c4])     = h01;
            *reinterpret_cast<__nv_bfloat162*>(&Ashi[r * LDSB + c4 + 2]) = h23;
            *reinterpret_cast<__nv_bfloat162*>(&Aslo[r * LDSB + c4])     = l01;
            *reinterpret_cast<__nv_bfloat162*>(&Aslo[r * LDSB + c4 + 2]) = l23;
        }
        // ---- stage B chunk: WT[n][kc..kc+31] bf16 hi/lo ----
        // 128 rows x 32 bf16 = 512 uint4 chunks: 4 chunks/row.
        #pragma unroll
        for (int j = 0; j < 2; j++) {
            int idx = t + 256 * j;        // 0..511
            int n   = idx >> 2;           // 0..127
            int k8  = (idx & 3) * 8;      // 0,8,16,24
            uint4 vh = *reinterpret_cast<const uint4*>(WhiT + n * D + kc + k8);
            uint4 vl = *reinterpret_cast<const uint4*>(WloT + n * D + kc + k8);
            *reinterpret_cast<uint4*>(&Bshi[n * LDSB + k8]) = vh;
            *reinterpret_cast<uint4*>(&Bslo[n * LDSB + k8]) = vl;
        }
        __syncthreads();

        // ---- compute: 2 k16 steps ----
        #pragma unroll
        for (int kk = 0; kk < 32; kk += 16) {
            uint32_t afh[2][4], afl[2][4];
            #pragma unroll
            for (int mt = 0; mt < 2; mt++) {
                int ar = wr * 32 + mt * 16;
                int k0 = kk + l2;
                afh[mt][0] = *reinterpret_cast<const uint32_t*>(&Ashi[(ar + l4)     * LDSB + k0]);
                afh[mt][1] = *reinterpret_cast<const uint32_t*>(&Ashi[(ar + l4 + 8) * LDSB + k0]);
                afh[mt][2] = *reinterpret_cast<const uint32_t*>(&Ashi[(ar + l4)     * LDSB + k0 + 8]);
                afh[mt][3] = *reinterpret_cast<const uint32_t*>(&Ashi[(ar + l4 + 8) * LDSB + k0 + 8]);
                afl[mt][0] = *reinterpret_cast<const uint32_t*>(&Aslo[(ar + l4)     * LDSB + k0]);
                afl[mt][1] = *reinterpret_cast<const uint32_t*>(&Aslo[(ar + l4 + 8) * LDSB + k0]);
                afl[mt][2] = *reinterpret_cast<const uint32_t*>(&Aslo[(ar + l4)     * LDSB + k0 + 8]);
                afl[mt][3] = *reinterpret_cast<const uint32_t*>(&Aslo[(ar + l4 + 8) * LDSB + k0 + 8]);
            }
            #pragma unroll
            for (int nt = 0; nt < 8; nt++) {
                int bn = wc * 64 + nt * 8 + l4;
                int k0 = kk + l2;
                uint32_t bfh[2], bfl[2];
                bfh[0] = *reinterpret_cast<const uint32_t*>(&Bshi[bn * LDSB + k0]);
                bfh[1] = *reinterpret_cast<const uint32_t*>(&Bshi[bn * LDSB + k0 + 8]);
                bfl[0] = *reinterpret_cast<const uint32_t*>(&Bslo[bn * LDSB + k0]);
                bfl[1] = *reinterpret_cast<const uint32_t*>(&Bslo[bn * LDSB + k0 + 8]);
                #pragma unroll
                for (int mt = 0; mt < 2; mt++) {
                    mma_bf16(acc[mt][nt], afh[mt], bfh);   // hi*hi
                    mma_bf16(acc[mt][nt], afh[mt], bfl);   // hi*lo
                    mma_bf16(acc[mt][nt], afl[mt], bfh);   // lo*hi
                }
            }
        }
        __syncthreads();
    }

    // ---- optional: zero our A rows (exclusively owned), prep next scatter ----
    if (zero_a) {
        const float4 z = make_float4(0.f, 0.f, 0.f, 0.f);
        #pragma unroll
        for (int j = 0; j < 16; j++) {
            int idx = t + 256 * j;        // float4 index 0..4095
            int r   = idx >> 5;           // row 0..127
            int c4  = (idx & 31) * 4;
            int gr  = row0 + r;
            if (gr < N_NODES)
                *reinterpret_cast<float4*>(A + (size_t)gr * D + c4) = z;
        }
    }

    // ---- epilogue: scale by inv_sqrt_in[row], + bias, relu, store ----
    #pragma unroll
    for (int mt = 0; mt < 2; mt++) {
        int gr0 = row0 + wr * 32 + mt * 16 + l4;
        int gr1 = gr0 + 8;
        float s0 = (gr0 < N_NODES) ? g_inv_in[gr0] : 0.0f;
        float s1 = (gr1 < N_NODES) ? g_inv_in[gr1] : 0.0f;
        #pragma unroll
        for (int nt = 0; nt < 8; nt++) {
            int col = wc * 64 + nt * 8 + l2;
            float2 bb = *reinterpret_cast<const float2*>(bias + col);
            float o0 = acc[mt][nt][0] * s0 + bb.x;
            float o1 = acc[mt][nt][1] * s0 + bb.y;
            float o2 = acc[mt][nt][2] * s1 + bb.x;
            float o3 = acc[mt][nt][3] * s1 + bb.y;
            if (relu) {
                o0 = fmaxf(o0, 0.f); o1 = fmaxf(o1, 0.f);
                o2 = fmaxf(o2, 0.f); o3 = fmaxf(o3, 0.f);
            }
            if (gr0 < N_NODES)
                *reinterpret_cast<float2*>(out + (size_t)gr0 * D + col) = make_float2(o0, o1);
            if (gr1 < N_NODES)
                *reinterpret_cast<float2*>(out + (size_t)gr1 * D + col) = make_float2(o2, o3);
        }
    }
}

// ---------------------------------------------------------------------------
// Launch sequence (graph-capturable)
// Inputs (metadata order): t, h, src, dst, W1, b1, W2, b2
// ---------------------------------------------------------------------------
extern "C" void kernel_launch(void* const* d_in, const int* in_sizes, int n_in,
                              void* d_out, int out_size) {
    const float* h   = (const float*)d_in[1];
    const int*   src = (const int*)  d_in[2];
    const int*   dst = (const int*)  d_in[3];
    const float* W1  = (const float*)d_in[4];
    const float* b1  = (const float*)d_in[5];
    const float* W2  = (const float*)d_in[6];
    const float* b2  = (const float*)d_in[7];
    float* out = (float*)d_out;

    static float* p_agg = nullptr;
    static float* p_h1  = nullptr;
    if (!p_agg) {
        void* pa = nullptr; void* ph = nullptr;
        cudaGetSymbolAddress(&pa, g_agg);
        cudaGetSymbolAddress(&ph, g_h1);
        p_agg = (float*)pa;
        p_h1  = (float*)ph;
    }

    const int TB = 256;
    const int blocks_nodes = (N_NODES + TB - 1) / TB;
    const int blocks_edges = (N_EDGES + TB - 1) / TB;
    const int blocks_init  = (int)(((size_t)N_NODES * D / 4 + TB - 1) / TB);
    const int blocks_gemm  = (N_NODES + 127) / 128;      // 782
    const int blocks_w     = (2 * D * D + TB - 1) / TB;  // 128

    // init + degrees + normalization + W pre-split
    init_kernel<<<blocks_init, TB>>>();
    degree_kernel<<<blocks_edges, TB>>>(src, dst);
    invsqrt_kernel<<<blocks_nodes, TB>>>();
    convert_w_kernel<<<blocks_w, TB>>>(W1, W2);

    // layer 1 (gemm zeroes g_agg behind itself for layer 2)
    scatter_kernel<<<blocks_edges, TB>>>(h, src, dst);
    gemm_tc_kernel<<<blocks_gemm, TB>>>(p_agg, 0, b1, p_h1, /*relu=*/1, /*zero_a=*/1);

    // layer 2
    scatter_kernel<<<blocks_edges, TB>>>(p_h1, src, dst);
    gemm_tc_kernel<<<blocks_gemm, TB>>>(p_agg, 1, b2, out, /*relu=*/0, /*zero_a=*/0);
}

// round 7
// speedup vs baseline: 1.8316x; 1.2523x over previous
#include <cuda_runtime.h>
#include <cuda_bf16.h>
#include <cstdint>

// Problem constants (fixed by the reference)
constexpr int N_NODES = 100000;
constexpr int N_EDGES = 640000;
constexpr int D       = 128;

constexpr int SCAN_B  = 256;
constexpr int NBLK    = (N_NODES + SCAN_B - 1) / SCAN_B;   // 391

// ---------------------------------------------------------------------------
// Scratch (allocation-free: __device__ globals)
// ---------------------------------------------------------------------------
__device__ int   g_ideg_out[N_NODES];
__device__ int   g_ideg_in [N_NODES];
__device__ float g_inv_out[N_NODES];
__device__ float g_inv_in [N_NODES];
__device__ int   g_off   [N_NODES + 1];   // CSR row offsets (by dst)
__device__ int   g_cursor[N_NODES];
__device__ int   g_csr   [N_EDGES];       // src indices grouped by dst
__device__ int   g_bsum  [512];           // scan partials
__device__ float g_agg[(size_t)N_NODES * D];   // aggregation result
__device__ float g_h1 [(size_t)N_NODES * D];   // layer-1 activations
// W split to bf16 hi/lo, stored TRANSPOSED: [n][k]
__device__ __nv_bfloat16 g_whiT[2][D * D];
__device__ __nv_bfloat16 g_wloT[2][D * D];

// ---------------------------------------------------------------------------
// Init: zero integer degree counters
// ---------------------------------------------------------------------------
__global__ void init_kernel() {
    int i = blockIdx.x * blockDim.x + threadIdx.x;
    if (i < N_NODES) { g_ideg_out[i] = 0; g_ideg_in[i] = 0; }
}

__global__ void degree_kernel(const int* __restrict__ src,
                              const int* __restrict__ dst) {
    int i = blockIdx.x * blockDim.x + threadIdx.x;
    if (i < N_EDGES) {
        atomicAdd(&g_ideg_out[src[i]], 1);
        atomicAdd(&g_ideg_in [dst[i]], 1);
    }
}

__global__ void invsqrt_kernel() {
    int i = blockIdx.x * blockDim.x + threadIdx.x;
    if (i < N_NODES) {
        g_inv_out[i] = rsqrtf((float)max(g_ideg_out[i], 1));
        g_inv_in [i] = rsqrtf((float)max(g_ideg_in [i], 1));
    }
}

// ---------------------------------------------------------------------------
// CSR build: 3-kernel scan of in-degrees + atomic-cursor fill
// ---------------------------------------------------------------------------
__global__ void scan_block_kernel() {
    __shared__ int sh[SCAN_B];
    int tid = threadIdx.x;
    int i   = blockIdx.x * SCAN_B + tid;
    int v   = (i < N_NODES) ? g_ideg_in[i] : 0;
    sh[tid] = v;
    __syncthreads();
    #pragma unroll
    for (int o = 1; o < SCAN_B; o <<= 1) {
        int t = (tid >= o) ? sh[tid - o] : 0;
        __syncthreads();
        sh[tid] += t;
        __syncthreads();
    }
    if (i < N_NODES) g_off[i] = sh[tid] - v;       // exclusive within block
    if (tid == SCAN_B - 1) g_bsum[blockIdx.x] = sh[tid];
}

__global__ void scan_partials_kernel() {
    __shared__ int sh[512];
    int tid = threadIdx.x;
    int v   = (tid < NBLK) ? g_bsum[tid] : 0;
    sh[tid] = v;
    __syncthreads();
    #pragma unroll
    for (int o = 1; o < 512; o <<= 1) {
        int t = (tid >= o) ? sh[tid - o] : 0;
        __syncthreads();
        sh[tid] += t;
        __syncthreads();
    }
    if (tid < NBLK) g_bsum[tid] = sh[tid] - v;     // exclusive block bases
}

__global__ void scan_add_kernel() {
    int i = blockIdx.x * blockDim.x + threadIdx.x;
    if (i < N_NODES) {
        int o = g_off[i] + g_bsum[i >> 8];
        g_off[i]    = o;
        g_cursor[i] = o;
    }
    if (i == 0) g_off[N_NODES] = N_EDGES;
}

__global__ void fill_csr_kernel(const int* __restrict__ src,
                                const int* __restrict__ dst) {
    int e = blockIdx.x * blockDim.x + threadIdx.x;
    if (e < N_EDGES) {
        int p = atomicAdd(&g_cursor[dst[e]], 1);
        g_csr[p] = src[e];
    }
}

// ---------------------------------------------------------------------------
// W pre-split, both layers, coalesced reads, transposed writes
// ---------------------------------------------------------------------------
__global__ void convert_w_kernel(const float* __restrict__ W1,
                                 const float* __restrict__ W2) {
    int idx = blockIdx.x * blockDim.x + threadIdx.x;
    if (idx < 2 * D * D) {
        int layer = idx >> 14;
        int r     = idx & (D * D - 1);
        int k = r >> 7;
        int n = r & (D - 1);
        const float* W = layer ? W2 : W1;
        float w = W[k * D + n];
        __nv_bfloat16 hi = __float2bfloat16(w);
        float lo = w - __bfloat162float(hi);
        g_whiT[layer][n * D + k] = hi;
        g_wloT[layer][n * D + k] = __float2bfloat16(lo);
    }
}

// ---------------------------------------------------------------------------
// Pull aggregation: agg[n] = inv_in[n] * sum_{s in in(n)} inv_out[s] * x[s]
// One warp per dst node; lane owns 4 contiguous features; register acc;
// single write per node. No atomics, no zeroing required.
// ---------------------------------------------------------------------------
__global__ void __launch_bounds__(256)
aggregate_kernel(const float* __restrict__ x) {
    int node = (blockIdx.x * blockDim.x + threadIdx.x) >> 5;
    int lane = threadIdx.x & 31;
    if (node >= N_NODES) return;

    int beg = g_off[node];
    int end = g_off[node + 1];
    const int c4 = lane * 4;

    float ax = 0.f, ay = 0.f, az = 0.f, aw = 0.f;
    int e = beg;
    for (; e + 2 <= end; e += 2) {
        int   s0 = g_csr[e];
        int   s1 = g_csr[e + 1];
        float c0 = g_inv_out[s0];
        float c1 = g_inv_out[s1];
        float4 v0 = *reinterpret_cast<const float4*>(x + (size_t)s0 * D + c4);
        float4 v1 = *reinterpret_cast<const float4*>(x + (size_t)s1 * D + c4);
        ax += v0.x * c0 + v1.x * c1;
        ay += v0.y * c0 + v1.y * c1;
        az += v0.z * c0 + v1.z * c1;
        aw += v0.w * c0 + v1.w * c1;
    }
    if (e < end) {
        int   s0 = g_csr[e];
        float c0 = g_inv_out[s0];
        float4 v0 = *reinterpret_cast<const float4*>(x + (size_t)s0 * D + c4);
        ax += v0.x * c0; ay += v0.y * c0; az += v0.z * c0; aw += v0.w * c0;
    }

    float si = g_inv_in[node];
    float4 o = make_float4(ax * si, ay * si, az * si, aw * si);
    *reinterpret_cast<float4*>(g_agg + (size_t)node * D + c4) = o;
}

// ---------------------------------------------------------------------------
// Tensor-core GEMM: out = relu?( A @ W + b )   (A = g_agg, already normalized)
// 3-product bf16 split emulation. CTA 128x128, 256 thr, warp 32x64.
// ---------------------------------------------------------------------------
__device__ __forceinline__ void mma_bf16(float* c, const uint32_t* a, const uint32_t* b) {
    asm volatile(
        "mma.sync.aligned.m16n8k16.row.col.f32.bf16.bf16.f32 "
        "{%0,%1,%2,%3}, {%4,%5,%6,%7}, {%8,%9}, {%0,%1,%2,%3};\n"
        : "+f"(c[0]), "+f"(c[1]), "+f"(c[2]), "+f"(c[3])
        : "r"(a[0]), "r"(a[1]), "r"(a[2]), "r"(a[3]), "r"(b[0]), "r"(b[1]));
}

constexpr int LDSB = 40;  // padded smem stride (bf16 units)

__global__ void __launch_bounds__(256, 2)
gemm_tc_kernel(const float* __restrict__ A, int layer,
               const float* __restrict__ bias,
               float*       __restrict__ out, int relu) {
    __shared__ __align__(16) __nv_bfloat16 Ashi[128 * LDSB];
    __shared__ __align__(16) __nv_bfloat16 Aslo[128 * LDSB];
    __shared__ __align__(16) __nv_bfloat16 Bshi[128 * LDSB];
    __shared__ __align__(16) __nv_bfloat16 Bslo[128 * LDSB];

    const int t    = threadIdx.x;
    const int lane = t & 31;
    const int w    = t >> 5;
    const int wr   = w >> 1;
    const int wc   = w & 1;
    const int row0 = blockIdx.x * 128;

    const __nv_bfloat16* WhiT = g_whiT[layer];
    const __nv_bfloat16* WloT = g_wloT[layer];

    float acc[2][8][4];
    #pragma unroll
    for (int mt = 0; mt < 2; mt++)
        #pragma unroll
        for (int nt = 0; nt < 8; nt++)
            #pragma unroll
            for (int r = 0; r < 4; r++) acc[mt][nt][r] = 0.0f;

    const int l4 = lane >> 2;
    const int l2 = (lane & 3) * 2;

    for (int kc = 0; kc < D; kc += 32) {
        #pragma unroll
        for (int j = 0; j < 4; j++) {
            int idx = t + 256 * j;
            int r   = idx >> 3;
            int c4  = (idx & 7) * 4;
            int gr  = row0 + r;
            float4 v = make_float4(0.f, 0.f, 0.f, 0.f);
            if (gr < N_NODES)
                v = *reinterpret_cast<const float4*>(A + (size_t)gr * D + kc + c4);
            __nv_bfloat16 hx = __float2bfloat16(v.x);
            __nv_bfloat16 hy = __float2bfloat16(v.y);
            __nv_bfloat16 hz = __float2bfloat16(v.z);
            __nv_bfloat16 hw = __float2bfloat16(v.w);
            __nv_bfloat162 h01; h01.x = hx; h01.y = hy;
            __nv_bfloat162 h23; h23.x = hz; h23.y = hw;
            __nv_bfloat162 l01, l23;
            l01.x = __float2bfloat16(v.x - __bfloat162float(hx));
            l01.y = __float2bfloat16(v.y - __bfloat162float(hy));
            l23.x = __float2bfloat16(v.z - __bfloat162float(hz));
            l23.y = __float2bfloat16(v.w - __bfloat162float(hw));
            *reinterpret_cast<__nv_bfloat162*>(&Ashi[r * LDSB + c4])     = h01;
            *reinterpret_cast<__nv_bfloat162*>(&Ashi[r * LDSB + c4 + 2]) = h23;
            *reinterpret_cast<__nv_bfloat162*>(&Aslo[r * LDSB + c4])     = l01;
            *reinterpret_cast<__nv_bfloat162*>(&Aslo[r * LDSB + c4 + 2]) = l23;
        }
        #pragma unroll
        for (int j = 0; j < 2; j++) {
            int idx = t + 256 * j;        // 0..511
            int n   = idx >> 2;           // 0..127
            int k8  = (idx & 3) * 8;      // 0,8,16,24
            uint4 vh = *reinterpret_cast<const uint4*>(WhiT + n * D + kc + k8);
            uint4 vl = *reinterpret_cast<const uint4*>(WloT + n * D + kc + k8);
            *reinterpret_cast<uint4*>(&Bshi[n * LDSB + k8]) = vh;
            *reinterpret_cast<uint4*>(&Bslo[n * LDSB + k8]) = vl;
        }
        __syncthreads();

        #pragma unroll
        for (int kk = 0; kk < 32; kk += 16) {
            uint32_t afh[2][4], afl[2][4];
            #pragma unroll
            for (int mt = 0; mt < 2; mt++) {
                int ar = wr * 32 + mt * 16;
                int k0 = kk + l2;
                afh[mt][0] = *reinterpret_cast<const uint32_t*>(&Ashi[(ar + l4)     * LDSB + k0]);
                afh[mt][1] = *reinterpret_cast<const uint32_t*>(&Ashi[(ar + l4 + 8) * LDSB + k0]);
                afh[mt][2] = *reinterpret_cast<const uint32_t*>(&Ashi[(ar + l4)     * LDSB + k0 + 8]);
                afh[mt][3] = *reinterpret_cast<const uint32_t*>(&Ashi[(ar + l4 + 8) * LDSB + k0 + 8]);
                afl[mt][0] = *reinterpret_cast<const uint32_t*>(&Aslo[(ar + l4)     * LDSB + k0]);
                afl[mt][1] = *reinterpret_cast<const uint32_t*>(&Aslo[(ar + l4 + 8) * LDSB + k0]);
                afl[mt][2] = *reinterpret_cast<const uint32_t*>(&Aslo[(ar + l4)     * LDSB + k0 + 8]);
                afl[mt][3] = *reinterpret_cast<const uint32_t*>(&Aslo[(ar + l4 + 8) * LDSB + k0 + 8]);
            }
            #pragma unroll
            for (int nt = 0; nt < 8; nt++) {
                int bn = wc * 64 + nt * 8 + l4;
                int k0 = kk + l2;
                uint32_t bfh[2], bfl[2];
                bfh[0] = *reinterpret_cast<const uint32_t*>(&Bshi[bn * LDSB + k0]);
                bfh[1] = *reinterpret_cast<const uint32_t*>(&Bshi[bn * LDSB + k0 + 8]);
                bfl[0] = *reinterpret_cast<const uint32_t*>(&Bslo[bn * LDSB + k0]);
                bfl[1] = *reinterpret_cast<const uint32_t*>(&Bslo[bn * LDSB + k0 + 8]);
                #pragma unroll
                for (int mt = 0; mt < 2; mt++) {
                    mma_bf16(acc[mt][nt], afh[mt], bfh);
                    mma_bf16(acc[mt][nt], afh[mt], bfl);
                    mma_bf16(acc[mt][nt], afl[mt], bfh);
                }
            }
        }
        __syncthreads();
    }

    // epilogue: + bias, relu, store
    #pragma unroll
    for (int mt = 0; mt < 2; mt++) {
        int gr0 = row0 + wr * 32 + mt * 16 + l4;
        int gr1 = gr0 + 8;
        #pragma unroll
        for (int nt = 0; nt < 8; nt++) {
            int col = wc * 64 + nt * 8 + l2;
            float2 bb = *reinterpret_cast<const float2*>(bias + col);
            float o0 = acc[mt][nt][0] + bb.x;
            float o1 = acc[mt][nt][1] + bb.y;
            float o2 = acc[mt][nt][2] + bb.x;
            float o3 = acc[mt][nt][3] + bb.y;
            if (relu) {
                o0 = fmaxf(o0, 0.f); o1 = fmaxf(o1, 0.f);
                o2 = fmaxf(o2, 0.f); o3 = fmaxf(o3, 0.f);
            }
            if (gr0 < N_NODES)
                *reinterpret_cast<float2*>(out + (size_t)gr0 * D + col) = make_float2(o0, o1);
            if (gr1 < N_NODES)
                *reinterpret_cast<float2*>(out + (size_t)gr1 * D + col) = make_float2(o2, o3);
        }
    }
}

// ---------------------------------------------------------------------------
// Launch sequence (graph-capturable)
// Inputs (metadata order): t, h, src, dst, W1, b1, W2, b2
// ---------------------------------------------------------------------------
extern "C" void kernel_launch(void* const* d_in, const int* in_sizes, int n_in,
                              void* d_out, int out_size) {
    const float* h   = (const float*)d_in[1];
    const int*   src = (const int*)  d_in[2];
    const int*   dst = (const int*)  d_in[3];
    const float* W1  = (const float*)d_in[4];
    const float* b1  = (const float*)d_in[5];
    const float* W2  = (const float*)d_in[6];
    const float* b2  = (const float*)d_in[7];
    float* out = (float*)d_out;

    static float* p_agg = nullptr;
    static float* p_h1  = nullptr;
    if (!p_agg) {
        void* pa = nullptr; void* ph = nullptr;
        cudaGetSymbolAddress(&pa, g_agg);
        cudaGetSymbolAddress(&ph, g_h1);
        p_agg = (float*)pa;
        p_h1  = (float*)ph;
    }

    const int TB = 256;
    const int blocks_nodes = (N_NODES + TB - 1) / TB;    // 391
    const int blocks_edges = (N_EDGES + TB - 1) / TB;    // 2500
    const int blocks_aggr  = (N_NODES * 32 + TB - 1) / TB; // warp per node
    const int blocks_gemm  = (N_NODES + 127) / 128;      // 782
    const int blocks_w     = (2 * D * D + TB - 1) / TB;  // 128

    // degrees, normalization, CSR build, W pre-split
    init_kernel<<<blocks_nodes, TB>>>();
    degree_kernel<<<blocks_edges, TB>>>(src, dst);
    invsqrt_kernel<<<blocks_nodes, TB>>>();
    scan_block_kernel<<<NBLK, SCAN_B>>>();
    scan_partials_kernel<<<1, 512>>>();
    scan_add_kernel<<<blocks_nodes, TB>>>();
    fill_csr_kernel<<<blocks_edges, TB>>>(src, dst);
    convert_w_kernel<<<blocks_w, TB>>>(W1, W2);

    // layer 1
    aggregate_kernel<<<blocks_aggr, TB>>>(h);
    gemm_tc_kernel<<<blocks_gemm, TB>>>(p_agg, 0, b1, p_h1, /*relu=*/1);

    // layer 2
    aggregate_kernel<<<blocks_aggr, TB>>>(p_h1);
    gemm_tc_kernel<<<blocks_gemm, TB>>>(p_agg, 1, b2, out, /*relu=*/0);
}

// round 8
// speedup vs baseline: 1.9121x; 1.0440x over previous
#include <cuda_runtime.h>
#include <cuda_bf16.h>
#include <cstdint>

// Problem constants (fixed by the reference)
constexpr int N_NODES = 100000;
constexpr int N_EDGES = 640000;
constexpr int D       = 128;

constexpr int SCAN_B  = 256;
constexpr int NBLK    = (N_NODES + SCAN_B - 1) / SCAN_B;   // 391

// ---------------------------------------------------------------------------
// Scratch (allocation-free: __device__ globals)
// ---------------------------------------------------------------------------
__device__ int   g_ideg_out[N_NODES];
__device__ int   g_ideg_in [N_NODES];
__device__ float g_inv_out[N_NODES];
__device__ float g_inv_in [N_NODES];
__device__ int   g_off   [N_NODES + 1];   // CSR row offsets (by dst)
__device__ int   g_cursor[N_NODES];
__device__ int   g_csr   [N_EDGES];       // src indices grouped by dst
__device__ int   g_bsum  [512];           // scan partials
// Aggregation result, pre-split to bf16 hi/lo (GEMM A operand)
__device__ __nv_bfloat16 g_ahi[(size_t)N_NODES * D];
__device__ __nv_bfloat16 g_alo[(size_t)N_NODES * D];
__device__ float g_h1 [(size_t)N_NODES * D];   // layer-1 activations (fp32)
// W split to bf16 hi/lo, stored TRANSPOSED: [n][k]
__device__ __nv_bfloat16 g_whiT[2][D * D];
__device__ __nv_bfloat16 g_wloT[2][D * D];

// ---------------------------------------------------------------------------
// Init + degrees
// ---------------------------------------------------------------------------
__global__ void init_kernel() {
    int i = blockIdx.x * blockDim.x + threadIdx.x;
    if (i < N_NODES) { g_ideg_out[i] = 0; g_ideg_in[i] = 0; }
}

__global__ void degree_kernel(const int* __restrict__ src,
                              const int* __restrict__ dst) {
    int i = blockIdx.x * blockDim.x + threadIdx.x;
    if (i < N_EDGES) {
        atomicAdd(&g_ideg_out[src[i]], 1);
        atomicAdd(&g_ideg_in [dst[i]], 1);
    }
}

// ---------------------------------------------------------------------------
// Block scan of in-degrees (shuffle-based) + fused inv-sqrt computation
// ---------------------------------------------------------------------------
__global__ void scan_block_kernel() {
    int tid  = threadIdx.x;
    int i    = blockIdx.x * SCAN_B + tid;
    int lane = tid & 31;
    int wid  = tid >> 5;

    int v = (i < N_NODES) ? g_ideg_in[i] : 0;
    if (i < N_NODES) {
        g_inv_out[i] = rsqrtf((float)max(g_ideg_out[i], 1));
        g_inv_in [i] = rsqrtf((float)max(v, 1));
    }

    // warp inclusive scan
    int x = v;
    #pragma unroll
    for (int o = 1; o < 32; o <<= 1) {
        int t = __shfl_up_sync(0xffffffffu, x, o);
        if (lane >= o) x += t;
    }
    __shared__ int wsum[8];
    if (lane == 31) wsum[wid] = x;
    __syncthreads();
    if (wid == 0 && lane < 8) {
        int y = wsum[lane];
        #pragma unroll
        for (int o = 1; o < 8; o <<= 1) {
            int t = __shfl_up_sync(0xffu, y, o);
            if (lane >= o) y += t;
        }
        wsum[lane] = y;
    }
    __syncthreads();
    int base = wid ? wsum[wid - 1] : 0;
    int incl = x + base;
    if (i < N_NODES) g_off[i] = incl - v;          // exclusive within block
    if (tid == SCAN_B - 1) g_bsum[blockIdx.x] = incl;
}

__global__ void scan_partials_kernel() {
    __shared__ int sh[512];
    int tid = threadIdx.x;
    int v   = (tid < NBLK) ? g_bsum[tid] : 0;
    sh[tid] = v;
    __syncthreads();
    #pragma unroll
    for (int o = 1; o < 512; o <<= 1) {
        int t = (tid >= o) ? sh[tid - o] : 0;
        __syncthreads();
        sh[tid] += t;
        __syncthreads();
    }
    if (tid < NBLK) g_bsum[tid] = sh[tid] - v;     // exclusive block bases
}

__global__ void scan_add_kernel() {
    int i = blockIdx.x * blockDim.x + threadIdx.x;
    if (i < N_NODES) {
        int o = g_off[i] + g_bsum[i >> 8];
        g_off[i]    = o;
        g_cursor[i] = o;
    }
    if (i == 0) g_off[N_NODES] = N_EDGES;
}

__global__ void fill_csr_kernel(const int* __restrict__ src,
                                const int* __restrict__ dst) {
    int e = blockIdx.x * blockDim.x + threadIdx.x;
    if (e < N_EDGES) {
        int p = atomicAdd(&g_cursor[dst[e]], 1);
        g_csr[p] = src[e];
    }
}

// ---------------------------------------------------------------------------
// W pre-split, both layers, coalesced reads, transposed writes
// ---------------------------------------------------------------------------
__global__ void convert_w_kernel(const float* __restrict__ W1,
                                 const float* __restrict__ W2) {
    int idx = blockIdx.x * blockDim.x + threadIdx.x;
    if (idx < 2 * D * D) {
        int layer = idx >> 14;
        int r     = idx & (D * D - 1);
        int k = r >> 7;
        int n = r & (D - 1);
        const float* W = layer ? W2 : W1;
        float w = W[k * D + n];
        __nv_bfloat16 hi = __float2bfloat16(w);
        float lo = w - __bfloat162float(hi);
        g_whiT[layer][n * D + k] = hi;
        g_wloT[layer][n * D + k] = __float2bfloat16(lo);
    }
}

// ---------------------------------------------------------------------------
// Pull aggregation: a[n] = inv_in[n] * sum_{s in in(n)} inv_out[s] * x[s]
// One warp per dst node; lane owns 4 features; register acc; writes the
// result PRE-SPLIT to bf16 hi/lo (GEMM A operand format).
// ---------------------------------------------------------------------------
__global__ void __launch_bounds__(256)
aggregate_kernel(const float* __restrict__ x) {
    int node = (blockIdx.x * blockDim.x + threadIdx.x) >> 5;
    int lane = threadIdx.x & 31;
    if (node >= N_NODES) return;

    int beg = g_off[node];
    int end = g_off[node + 1];
    const int c4 = lane * 4;

    float ax = 0.f, ay = 0.f, az = 0.f, aw = 0.f;
    int e = beg;
    for (; e + 2 <= end; e += 2) {
        int   s0 = g_csr[e];
        int   s1 = g_csr[e + 1];
        float c0 = g_inv_out[s0];
        float c1 = g_inv_out[s1];
        float4 v0 = *reinterpret_cast<const float4*>(x + (size_t)s0 * D + c4);
        float4 v1 = *reinterpret_cast<const float4*>(x + (size_t)s1 * D + c4);
        ax += v0.x * c0 + v1.x * c1;
        ay += v0.y * c0 + v1.y * c1;
        az += v0.z * c0 + v1.z * c1;
        aw += v0.w * c0 + v1.w * c1;
    }
    if (e < end) {
        int   s0 = g_csr[e];
        float c0 = g_inv_out[s0];
        float4 v0 = *reinterpret_cast<const float4*>(x + (size_t)s0 * D + c4);
        ax += v0.x * c0; ay += v0.y * c0; az += v0.z * c0; aw += v0.w * c0;
    }

    float si = g_inv_in[node];
    ax *= si; ay *= si; az *= si; aw *= si;

    __nv_bfloat162 h01, h23, l01, l23;
    h01.x = __float2bfloat16(ax); h01.y = __float2bfloat16(ay);
    h23.x = __float2bfloat16(az); h23.y = __float2bfloat16(aw);
    l01.x = __float2bfloat16(ax - __bfloat162float(h01.x));
    l01.y = __float2bfloat16(ay - __bfloat162float(h01.y));
    l23.x = __float2bfloat16(az - __bfloat162float(h23.x));
    l23.y = __float2bfloat16(aw - __bfloat162float(h23.y));

    uint2 vh, vl;
    vh.x = *reinterpret_cast<uint32_t*>(&h01);
    vh.y = *reinterpret_cast<uint32_t*>(&h23);
    vl.x = *reinterpret_cast<uint32_t*>(&l01);
    vl.y = *reinterpret_cast<uint32_t*>(&l23);
    *reinterpret_cast<uint2*>(g_ahi + (size_t)node * D + c4) = vh;
    *reinterpret_cast<uint2*>(g_alo + (size_t)node * D + c4) = vl;
}

// ---------------------------------------------------------------------------
// Tensor-core GEMM: out = relu?( A @ W + b ), A pre-split bf16 hi/lo.
// cp.async double-buffered staging (2 stages x {Ahi,Alo,Bhi,Blo}).
// CTA 128x128, 256 thr, warp 32x64. 3-product bf16 emulation.
// ---------------------------------------------------------------------------
__device__ __forceinline__ void mma_bf16(float* c, const uint32_t* a, const uint32_t* b) {
    asm volatile(
        "mma.sync.aligned.m16n8k16.row.col.f32.bf16.bf16.f32 "
        "{%0,%1,%2,%3}, {%4,%5,%6,%7}, {%8,%9}, {%0,%1,%2,%3};\n"
        : "+f"(c[0]), "+f"(c[1]), "+f"(c[2]), "+f"(c[3])
        : "r"(a[0]), "r"(a[1]), "r"(a[2]), "r"(a[3]), "r"(b[0]), "r"(b[1]));
}

__device__ __forceinline__ void cp16(uint32_t smem, const void* gptr, int src_bytes) {
    asm volatile("cp.async.ca.shared.global [%0], [%1], 16, %2;\n"
                 :: "r"(smem), "l"(gptr), "r"(src_bytes));
}

constexpr int LDSB = 40;  // padded smem stride (bf16 units), conflict-free

__global__ void __launch_bounds__(256, 2)
gemm_tc_kernel(int layer, const float* __restrict__ bias,
               float* __restrict__ out, int relu) {
    // [stage][0=Ahi,1=Alo,2=Bhi,3=Blo]
    __shared__ __align__(16) __nv_bfloat16 sm[2][4][128 * LDSB];

    const int t    = threadIdx.x;
    const int lane = t & 31;
    const int w    = t >> 5;
    const int wr   = w >> 1;
    const int wc   = w & 1;
    const int row0 = blockIdx.x * 128;

    const __nv_bfloat16* WhiT = g_whiT[layer];
    const __nv_bfloat16* WloT = g_wloT[layer];

    // stage chunk c (k = c*32..c*32+31) into stage s
    auto stage_chunk = [&](int c, int s) {
        const int kc = c * 32;
        #pragma unroll
        for (int j = 0; j < 2; j++) {
            int idx = t + 256 * j;        // 0..511
            int r   = idx >> 2;           // 0..127 (A row / B col-row)
            int k8  = (idx & 3) * 8;      // 0,8,16,24
            int gr  = row0 + r;
            int ok  = (gr < N_NODES) ? 16 : 0;
            size_t ga = (size_t)min(gr, N_NODES - 1) * D + kc + k8;
            uint32_t so = (uint32_t)((r * LDSB + k8) * 2);
            cp16((uint32_t)__cvta_generic_to_shared(&sm[s][0][0]) + so, g_ahi + ga, ok);
            cp16((uint32_t)__cvta_generic_to_shared(&sm[s][1][0]) + so, g_alo + ga, ok);
            cp16((uint32_t)__cvta_generic_to_shared(&sm[s][2][0]) + so, WhiT + r * D + kc + k8, 16);
            cp16((uint32_t)__cvta_generic_to_shared(&sm[s][3][0]) + so, WloT + r * D + kc + k8, 16);
        }
        asm volatile("cp.async.commit_group;\n");
    };

    float acc[2][8][4];
    #pragma unroll
    for (int mt = 0; mt < 2; mt++)
        #pragma unroll
        for (int nt = 0; nt < 8; nt++)
            #pragma unroll
            for (int r = 0; r < 4; r++) acc[mt][nt][r] = 0.0f;

    const int l4 = lane >> 2;
    const int l2 = (lane & 3) * 2;

    stage_chunk(0, 0);
    stage_chunk(1, 1);

    #pragma unroll
    for (int c = 0; c < 4; c++) {
        const int s = c & 1;
        if (c < 3) asm volatile("cp.async.wait_group 1;\n");
        else       asm volatile("cp.async.wait_group 0;\n");
        __syncthreads();

        const __nv_bfloat16* Ashi = sm[s][0];
        const __nv_bfloat16* Aslo = sm[s][1];
        const __nv_bfloat16* Bshi = sm[s][2];
        const __nv_bfloat16* Bslo = sm[s][3];

        #pragma unroll
        for (int kk = 0; kk < 32; kk += 16) {
            uint32_t afh[2][4], afl[2][4];
            #pragma unroll
            for (int mt = 0; mt < 2; mt++) {
                int ar = wr * 32 + mt * 16;
                int k0 = kk + l2;
                afh[mt][0] = *reinterpret_cast<const uint32_t*>(&Ashi[(ar + l4)     * LDSB + k0]);
                afh[mt][1] = *reinterpret_cast<const uint32_t*>(&Ashi[(ar + l4 + 8) * LDSB + k0]);
                afh[mt][2] = *reinterpret_cast<const uint32_t*>(&Ashi[(ar + l4)     * LDSB + k0 + 8]);
                afh[mt][3] = *reinterpret_cast<const uint32_t*>(&Ashi[(ar + l4 + 8) * LDSB + k0 + 8]);
                afl[mt][0] = *reinterpret_cast<const uint32_t*>(&Aslo[(ar + l4)     * LDSB + k0]);
                afl[mt][1] = *reinterpret_cast<const uint32_t*>(&Aslo[(ar + l4 + 8) * LDSB + k0]);
                afl[mt][2] = *reinterpret_cast<const uint32_t*>(&Aslo[(ar + l4)     * LDSB + k0 + 8]);
                afl[mt][3] = *reinterpret_cast<const uint32_t*>(&Aslo[(ar + l4 + 8) * LDSB + k0 + 8]);
            }
            #pragma unroll
            for (int nt = 0; nt < 8; nt++) {
                int bn = wc * 64 + nt * 8 + l4;
                int k0 = kk + l2;
                uint32_t bfh[2], bfl[2];
                bfh[0] = *reinterpret_cast<const uint32_t*>(&Bshi[bn * LDSB + k0]);
                bfh[1] = *reinterpret_cast<const uint32_t*>(&Bshi[bn * LDSB + k0 + 8]);
                bfl[0] = *reinterpret_cast<const uint32_t*>(&Bslo[bn * LDSB + k0]);
                bfl[1] = *reinterpret_cast<const uint32_t*>(&Bslo[bn * LDSB + k0 + 8]);
                #pragma unroll
                for (int mt = 0; mt < 2; mt++) {
                    mma_bf16(acc[mt][nt], afh[mt], bfh);
                    mma_bf16(acc[mt][nt], afh[mt], bfl);
                    mma_bf16(acc[mt][nt], afl[mt], bfh);
                }
            }
        }
        __syncthreads();
        if (c < 2) stage_chunk(c + 2, s);
    }

    // epilogue: + bias, relu, store
    #pragma unroll
    for (int mt = 0; mt < 2; mt++) {
        int gr0 = row0 + wr * 32 + mt * 16 + l4;
        int gr1 = gr0 + 8;
        #pragma unroll
        for (int nt = 0; nt < 8; nt++) {
            int col = wc * 64 + nt * 8 + l2;
            float2 bb = *reinterpret_cast<const float2*>(bias + col);
            float o0 = acc[mt][nt][0] + bb.x;
            float o1 = acc[mt][nt][1] + bb.y;
            float o2 = acc[mt][nt][2] + bb.x;
            float o3 = acc[mt][nt][3] + bb.y;
            if (relu) {
                o0 = fmaxf(o0, 0.f); o1 = fmaxf(o1, 0.f);
                o2 = fmaxf(o2, 0.f); o3 = fmaxf(o3, 0.f);
            }
            if (gr0 < N_NODES)
                *reinterpret_cast<float2*>(out + (size_t)gr0 * D + col) = make_float2(o0, o1);
            if (gr1 < N_NODES)
                *reinterpret_cast<float2*>(out + (size_t)gr1 * D + col) = make_float2(o2, o3);
        }
    }
}

// ---------------------------------------------------------------------------
// Launch sequence (graph-capturable)
// Inputs (metadata order): t, h, src, dst, W1, b1, W2, b2
// ---------------------------------------------------------------------------
extern "C" void kernel_launch(void* const* d_in, const int* in_sizes, int n_in,
                              void* d_out, int out_size) {
    const float* h   = (const float*)d_in[1];
    const int*   src = (const int*)  d_in[2];
    const int*   dst = (const int*)  d_in[3];
    const float* W1  = (const float*)d_in[4];
    const float* b1  = (const float*)d_in[5];
    const float* W2  = (const float*)d_in[6];
    const float* b2  = (const float*)d_in[7];
    float* out = (float*)d_out;

    static float* p_h1 = nullptr;
    if (!p_h1) {
        void* ph = nullptr;
        cudaGetSymbolAddress(&ph, g_h1);
        p_h1 = (float*)ph;
    }

    const int TB = 256;
    const int blocks_nodes = (N_NODES + TB - 1) / TB;      // 391
    const int blocks_edges = (N_EDGES + TB - 1) / TB;      // 2500
    const int blocks_aggr  = (N_NODES * 32 + TB - 1) / TB; // warp per node
    const int blocks_gemm  = (N_NODES + 127) / 128;        // 782
    const int blocks_w     = (2 * D * D + TB - 1) / TB;    // 128

    // degrees, normalization, CSR build, W pre-split
    init_kernel<<<blocks_nodes, TB>>>();
    degree_kernel<<<blocks_edges, TB>>>(src, dst);
    scan_block_kernel<<<NBLK, SCAN_B>>>();         // + invsqrt fused
    scan_partials_kernel<<<1, 512>>>();
    scan_add_kernel<<<blocks_nodes, TB>>>();
    fill_csr_kernel<<<blocks_edges, TB>>>(src, dst);
    convert_w_kernel<<<blocks_w, TB>>>(W1, W2);

    // layer 1
    aggregate_kernel<<<blocks_aggr, TB>>>(h);
    gemm_tc_kernel<<<blocks_gemm, TB>>>(0, b1, p_h1, /*relu=*/1);

    // layer 2
    aggregate_kernel<<<blocks_aggr, TB>>>(p_h1);
    gemm_tc_kernel<<<blocks_gemm, TB>>>(1, b2, out, /*relu=*/0);
}